// round 16
// baseline (speedup 1.0000x reference)
#include <cuda_runtime.h>
#include <cuda_bf16.h>
#include <cstdint>

// ---------------------------------------------------------------------------
// Problem constants
#define NRED   100000
#define TT     32
#define KFEAT  512
#define THRESH 10.0f
#define KWTA   16

// GEMM tiling: 74 k-splits x 4 m-tiles = 296 CTAs (2 CTAs/SM)
#define SPLITS 74
#define KTILE  64
#define NT     22
#define CHUNK  (KTILE * NT)        // 1408
#define MTILE  128

#define SM_A    0
#define SM_ASTG 32768
#define SM_B    (2 * SM_ASTG)      // 65536
#define SM_BSTG 8192
#define SMEMB   (SM_B + 2 * SM_BSTG)   // 81920

#define RS_BLOCKS 128              // reduce_sel grid

// Device scratch (static — no dynamic allocation allowed)
__device__ float g_partial[SPLITS * TT * KFEAT];
__device__ float g_dot[TT * KFEAT];                // [t][feat]
__device__ int   g_arrive;                         // last-block counter

typedef unsigned long long ull;

// ---------------------------------------------------------------------------
__device__ __forceinline__ uint32_t smem_u32(const void* p) {
    uint32_t a;
    asm("{ .reg .u64 t; cvta.to.shared.u64 t, %1; cvt.u32.u64 %0, t; }"
        : "=r"(a) : "l"(p));
    return a;
}
__device__ __forceinline__ uint32_t sw128(uint32_t off) {
    return off ^ ((off >> 3) & 0x70);
}
__device__ __forceinline__ uint32_t packbf(__nv_bfloat16 a, __nv_bfloat16 b) {
    __nv_bfloat162 v; v.x = a; v.y = b;
    return *reinterpret_cast<uint32_t*>(&v);
}
__device__ __forceinline__ void split2(float x, __nv_bfloat16& h, __nv_bfloat16& l) {
    h = __float2bfloat16(x);
    l = __float2bfloat16(x - __bfloat162float(h));
}
#define LDSM4(R, ADDR)                                                        \
    asm volatile("ldmatrix.sync.aligned.m8n8.x4.shared.b16 {%0,%1,%2,%3}, [%4];" \
                 : "=r"((R)[0]), "=r"((R)[1]), "=r"((R)[2]), "=r"((R)[3])     \
                 : "r"(ADDR))
#define MMA16816(D, A, B0, B1)                                                \
    asm volatile("mma.sync.aligned.m16n8k16.row.col.f32.bf16.bf16.f32 "       \
                 "{%0,%1,%2,%3}, {%4,%5,%6,%7}, {%8,%9}, {%0,%1,%2,%3};"      \
                 : "+f"((D)[0]), "+f"((D)[1]), "+f"((D)[2]), "+f"((D)[3])     \
                 : "r"((A)[0]), "r"((A)[1]), "r"((A)[2]), "r"((A)[3]),        \
                   "r"(B0), "r"(B1))

// ---------------------------------------------------------------------------
// GEMM: bf16 3-term split, balanced across warp groups:
//   grp0: ah x bh (all ks) + al x bh (ks 0-1)
//   grp1: ah x bl (all ks) + al x bh (ks 2-3)
// Epilogue fold (d_grp0 + d_grp1) sums the terms — exact.
// grid (74, 4), 256 threads, 2 CTAs/SM.
// ---------------------------------------------------------------------------
__global__ void __launch_bounds__(256, 2)
gemm_kernel(const float* __restrict__ W, const float* __restrict__ R) {
    extern __shared__ char smem[];
    const uint32_t sb = smem_u32(smem);

    const int tid  = threadIdx.x;
    const int lane = tid & 31;
    const int wrp  = tid >> 5;
    const int q    = wrp & 3;
    const int grp  = wrp >> 2;
    const int split = blockIdx.x;
    const int m0    = blockIdx.y * MTILE;
    const int kbase = split * CHUNK;

    if (split == 0 && blockIdx.y == 0 && tid == 0) g_arrive = 0;

    const int row_off = lane >> 4;
    const int kq      = lane & 15;
    const int bt  = tid >> 3;
    const int bkc = tid & 7;
    const uint32_t bo = (uint32_t)bt * 128 + (uint32_t)bkc * 16;

    const int s0 = 2 * q, s1 = 2 * q + 1;
    const int arow0 = s0 * 16 + (lane & 7) + ((lane >> 3) & 1) * 8;
    const int arow1 = s1 * 16 + (lane & 7) + ((lane >> 3) & 1) * 8;
    const uint32_t a_kb0 = ((lane >> 4) & 1) * 16;
    const uint32_t a_off0 = (uint32_t)arow0 * 128;
    const uint32_t a_off1 = (uint32_t)arow1 * 128;
    const uint32_t a_xr0  = (uint32_t)(arow0 & 7) << 4;
    const uint32_t a_xr1  = (uint32_t)(arow1 & 7) << 4;
    const int browl = (lane & 7) + ((lane >> 4) & 1) * 8;
    const uint32_t b_rb  = (uint32_t)browl * 128;      // bh plane base
    const uint32_t b_xr  = (uint32_t)(lane & 7) << 4;
    const uint32_t b_kb0 = ((lane >> 3) & 1) * 16;

    float d[2][4][4];
#pragma unroll
    for (int s = 0; s < 2; s++)
#pragma unroll
        for (int i = 0; i < 4; i++)
#pragma unroll
            for (int j = 0; j < 4; j++) d[s][i][j] = 0.0f;

    float4 wr[8];
    float4 br0, br1;
    const float4 z4 = make_float4(0.f, 0.f, 0.f, 0.f);

#define LOAD_W(TL) do {                                                      \
    const int kp_ = kbase + (TL) * KTILE + kq * 4;                           \
    const bool ok_ = (kp_ < NRED);                                           \
    const float* wp_ = W + (size_t)(m0 + wrp * 2 + row_off) * NRED + kp_;    \
    _Pragma("unroll")                                                        \
    for (int i = 0; i < 8; i++)                                              \
        wr[i] = ok_ ? *(const float4*)(wp_ + (size_t)16 * i * NRED) : z4;    \
} while (0)

#define LOAD_B(TL) do {                                                      \
    const int kp_ = kbase + (TL) * KTILE + bkc * 8;                          \
    const bool ok_ = (kp_ < NRED);                                           \
    const float* rp_ = R + (size_t)bt * NRED + kp_;                          \
    br0 = ok_ ? *(const float4*)(rp_)     : z4;                              \
    br1 = ok_ ? *(const float4*)(rp_ + 4) : z4;                              \
} while (0)

#define STS_B(BUF) do {                                                      \
    char* bb_ = smem + SM_B + (BUF) * SM_BSTG;                               \
    __nv_bfloat16 h0,h1,h2,h3,h4,h5,h6,h7,l0,l1,l2,l3,l4,l5,l6,l7;           \
    split2(br0.x,h0,l0); split2(br0.y,h1,l1);                                \
    split2(br0.z,h2,l2); split2(br0.w,h3,l3);                                \
    split2(br1.x,h4,l4); split2(br1.y,h5,l5);                                \
    split2(br1.z,h6,l6); split2(br1.w,h7,l7);                                \
    *(uint4*)(bb_ + sw128(bo)) =                                             \
        make_uint4(packbf(h0,h1), packbf(h2,h3), packbf(h4,h5), packbf(h6,h7)); \
    *(uint4*)(bb_ + sw128(bo + 4096)) =                                      \
        make_uint4(packbf(l0,l1), packbf(l2,l3), packbf(l4,l5), packbf(l6,l7)); \
} while (0)

#define STS_A(BUF) do {                                                      \
    char* ab_ = smem + SM_A + (BUF) * SM_ASTG;                               \
    _Pragma("unroll")                                                        \
    for (int i = 0; i < 8; i++) {                                            \
        const int row_ = i * 16 + wrp * 2 + row_off;                         \
        const uint32_t sw_ = sw128((uint32_t)row_ * 128 + kq * 8);           \
        float4 f_ = wr[i];                                                   \
        __nv_bfloat16 h0,h1,h2,h3,l0,l1,l2,l3;                               \
        split2(f_.x, h0, l0); split2(f_.y, h1, l1);                          \
        split2(f_.z, h2, l2); split2(f_.w, h3, l3);                          \
        *(uint2*)(ab_ + sw_)         = make_uint2(packbf(h0,h1), packbf(h2,h3)); \
        *(uint2*)(ab_ + sw_ + 16384) = make_uint2(packbf(l0,l1), packbf(l2,l3)); \
    }                                                                        \
} while (0)

#define MMA8(DD, AA, BB) do {                                                \
    MMA16816((DD)[0], (AA), (BB)[0][0], (BB)[0][1]);                         \
    MMA16816((DD)[1], (AA), (BB)[0][2], (BB)[0][3]);                         \
    MMA16816((DD)[2], (AA), (BB)[1][0], (BB)[1][1]);                         \
    MMA16816((DD)[3], (AA), (BB)[1][2], (BB)[1][3]);                         \
} while (0)

#define COMPUTE(BUF) do {                                                    \
    const uint32_t sa_ = sb + SM_A + (BUF) * SM_ASTG;                        \
    const uint32_t sB_ = sb + SM_B + (BUF) * SM_BSTG;                        \
    _Pragma("unroll")                                                        \
    for (int ks = 0; ks < 4; ks++) {                                         \
        uint32_t ah0[4], ah1[4], bp[2][4];                                   \
        const uint32_t kb_ = (uint32_t)(ks * 32) + a_kb0;                    \
        LDSM4(ah0, sa_ + a_off0 + (kb_ ^ a_xr0));                            \
        LDSM4(ah1, sa_ + a_off1 + (kb_ ^ a_xr1));                            \
        const uint32_t bkb_ = ((uint32_t)(ks * 32) + b_kb0) ^ b_xr;          \
        if (grp == 0) {                                                      \
            LDSM4(bp[0], sB_ + b_rb + bkb_);                                 \
            LDSM4(bp[1], sB_ + 2048 + b_rb + bkb_);                          \
            MMA8(d[0], ah0, bp);                                             \
            MMA8(d[1], ah1, bp);                                             \
            if (ks < 2) {                                                    \
                uint32_t al0[4], al1[4];                                     \
                LDSM4(al0, sa_ + 16384 + a_off0 + (kb_ ^ a_xr0));            \
                LDSM4(al1, sa_ + 16384 + a_off1 + (kb_ ^ a_xr1));            \
                MMA8(d[0], al0, bp);                                         \
                MMA8(d[1], al1, bp);                                         \
            }                                                                \
        } else {                                                             \
            uint32_t bl[2][4];                                               \
            LDSM4(bl[0], sB_ + 4096 + b_rb + bkb_);                          \
            LDSM4(bl[1], sB_ + 4096 + 2048 + b_rb + bkb_);                   \
            MMA8(d[0], ah0, bl);                                             \
            MMA8(d[1], ah1, bl);                                             \
            if (ks >= 2) {                                                   \
                uint32_t al0[4], al1[4];                                     \
                LDSM4(al0, sa_ + 16384 + a_off0 + (kb_ ^ a_xr0));            \
                LDSM4(al1, sa_ + 16384 + a_off1 + (kb_ ^ a_xr1));            \
                LDSM4(bp[0], sB_ + b_rb + bkb_);                             \
                LDSM4(bp[1], sB_ + 2048 + b_rb + bkb_);                      \
                MMA8(d[0], al0, bp);                                         \
                MMA8(d[1], al1, bp);                                         \
            }                                                                \
        }                                                                    \
    }                                                                        \
} while (0)

    LOAD_B(0);
    LOAD_W(0);
    STS_B(0);
    STS_A(0);
    __syncthreads();

    for (int tl = 0; tl < NT; tl++) {
        if (tl + 1 < NT) {
            LOAD_B(tl + 1);
            LOAD_W(tl + 1);
        }
        COMPUTE(tl & 1);
        if (tl + 1 < NT) {
            STS_B((tl + 1) & 1);
            STS_A((tl + 1) & 1);
            __syncthreads();
        }
    }

    __syncthreads();
    float* es = (float*)smem;
    const int eidx = (q * 32 + lane) * 33;
    if (grp == 1) {
#pragma unroll
        for (int s = 0; s < 2; s++)
#pragma unroll
            for (int i = 0; i < 4; i++)
#pragma unroll
                for (int j = 0; j < 4; j++)
                    es[eidx + s * 16 + i * 4 + j] = d[s][i][j];
    }
    __syncthreads();
    if (grp == 0) {
        float* gp = g_partial + (size_t)split * (TT * KFEAT) + m0;
        const int rbase = lane >> 2;
        const int c0 = (lane & 3) * 2;
#pragma unroll
        for (int s = 0; s < 2; s++) {
            const int feat = (2 * q + s) * 16 + rbase;
#pragma unroll
            for (int nt = 0; nt < 4; nt++) {
                const int t0 = nt * 8 + c0;
                float v0 = d[s][nt][0] + es[eidx + s * 16 + nt * 4 + 0];
                float v1 = d[s][nt][1] + es[eidx + s * 16 + nt * 4 + 1];
                float v2 = d[s][nt][2] + es[eidx + s * 16 + nt * 4 + 2];
                float v3 = d[s][nt][3] + es[eidx + s * 16 + nt * 4 + 3];
                gp[(size_t)t0 * KFEAT + feat]           = v0;
                gp[(size_t)(t0 + 1) * KFEAT + feat]     = v1;
                gp[(size_t)t0 * KFEAT + feat + 8]       = v2;
                gp[(size_t)(t0 + 1) * KFEAT + feat + 8] = v3;
            }
        }
    }
}

// ---------------------------------------------------------------------------
// Fused reduce + selection. 128 blocks x 512 threads.
// ---------------------------------------------------------------------------
__global__ void __launch_bounds__(512, 1)
reduce_sel_kernel(float* __restrict__ out) {
    __shared__ float part_s[4][136];
    const int k = threadIdx.x;
    {
        const int jl = k & 127;
        const int p  = k >> 7;
        const int j  = blockIdx.x * 128 + jl;
        const int sp0 = (p * SPLITS) >> 2;
        const int sp1 = ((p + 1) * SPLITS) >> 2;
        float s = 0.0f;
#pragma unroll 8
        for (int sp = sp0; sp < sp1; sp++)
            s += g_partial[sp * (TT * KFEAT) + j];
        part_s[p][jl] = s;
        __syncthreads();
        if (k < 128) {
            float tot = ((part_s[0][k] + part_s[1][k])
                       + (part_s[2][k] + part_s[3][k]));
            g_dot[blockIdx.x * 128 + k] = tot;
        }
    }

    __shared__ int is_last;
    __threadfence();
    __syncthreads();
    if (k == 0) is_last = (atomicAdd(&g_arrive, 1) == RS_BLOCKS - 1);
    __syncthreads();
    if (!is_last) return;
    __threadfence();

    // ---- selection phase (this block only) ----
    __shared__ ull   key_s[KFEAT];
    __shared__ int   win_s[KFEAT];
    __shared__ float red_s[16];
    __shared__ float v_s;

    int nspk = 0;
#pragma unroll
    for (int t = 0; t < TT; t++) {
        float dd = g_dot[t * KFEAT + k];
        nspk += (dd > THRESH) ? 1 : 0;
    }
    int first = TT - nspk;
    if (first > TT - 1) first = TT - 1;
    if (first < 0) first = 0;
    float dv = g_dot[first * KFEAT + k];
    float value = (dv > THRESH) ? dv : 0.0f;
    float sval = (nspk > 0) ? value : 0.0f;

    float m = sval;
#pragma unroll
    for (int o = 16; o > 0; o >>= 1)
        m = fmaxf(m, __shfl_xor_sync(0xffffffffu, m, o));
    if ((k & 31) == 0) red_s[k >> 5] = m;
    win_s[k] = 0;
    __syncthreads();
    if (k == 0) {
        float mm = red_s[0];
#pragma unroll
        for (int i = 1; i < 16; i++) mm = fmaxf(mm, red_s[i]);
        v_s = mm * (float)TT;
    }
    __syncthreads();

    const float fns = (float)nspk;
    const float total = fns * value + fns * v_s;   // >= 0 always
    ull key = ((ull)__float_as_uint(total) << 32)
            | (ull)(KFEAT - 1 - k);

#define INTRA_STAGE(KK, J) do {                                              \
    ull other_ = __shfl_xor_sync(0xffffffffu, key, (J));                     \
    const bool up_ = ((k & (KK)) == 0);                                      \
    const bool lo_ = ((k & (J)) == 0);                                       \
    const bool keepmin_ = (up_ == lo_);                                      \
    key = keepmin_ ? (key < other_ ? key : other_)                           \
                   : (key > other_ ? key : other_);                          \
} while (0)

#define CROSS_STAGE(KK, J) do {                                              \
    key_s[k] = key;                                                          \
    __syncthreads();                                                         \
    ull other_ = key_s[k ^ (J)];                                             \
    const bool up_ = ((k & (KK)) == 0);                                      \
    const bool lo_ = ((k & (J)) == 0);                                       \
    const bool keepmin_ = (up_ == lo_);                                      \
    key = keepmin_ ? (key < other_ ? key : other_)                           \
                   : (key > other_ ? key : other_);                          \
    __syncthreads();                                                         \
} while (0)

    INTRA_STAGE(2, 1);
    INTRA_STAGE(4, 2);  INTRA_STAGE(4, 1);
    INTRA_STAGE(8, 4);  INTRA_STAGE(8, 2);  INTRA_STAGE(8, 1);
    INTRA_STAGE(16, 8); INTRA_STAGE(16, 4); INTRA_STAGE(16, 2); INTRA_STAGE(16, 1);
    INTRA_STAGE(32, 16); INTRA_STAGE(32, 8); INTRA_STAGE(32, 4);
    INTRA_STAGE(32, 2);  INTRA_STAGE(32, 1);
    CROSS_STAGE(64, 32);
    INTRA_STAGE(64, 16); INTRA_STAGE(64, 8); INTRA_STAGE(64, 4);
    INTRA_STAGE(64, 2);  INTRA_STAGE(64, 1);
    CROSS_STAGE(128, 64); CROSS_STAGE(128, 32);
    INTRA_STAGE(128, 16); INTRA_STAGE(128, 8); INTRA_STAGE(128, 4);
    INTRA_STAGE(128, 2);  INTRA_STAGE(128, 1);
    CROSS_STAGE(256, 128); CROSS_STAGE(256, 64); CROSS_STAGE(256, 32);
    INTRA_STAGE(256, 16); INTRA_STAGE(256, 8); INTRA_STAGE(256, 4);
    INTRA_STAGE(256, 2);  INTRA_STAGE(256, 1);
    CROSS_STAGE(512, 256); CROSS_STAGE(512, 128); CROSS_STAGE(512, 64);
    CROSS_STAGE(512, 32);
    INTRA_STAGE(512, 16); INTRA_STAGE(512, 8); INTRA_STAGE(512, 4);
    INTRA_STAGE(512, 2);  INTRA_STAGE(512, 1);

    if (k >= KFEAT - KWTA) {
        if ((uint32_t)(key >> 32) != 0u) {
            const int idx = KFEAT - 1 - (int)(key & 0x1ffull);
            win_s[idx] = 1;
        }
    }
    __syncthreads();

    const bool win = (win_s[k] != 0);
#pragma unroll
    for (int t = 0; t < TT; t++) {
        float dd = g_dot[t * KFEAT + k];
        out[t * KFEAT + k] = (win && dd > THRESH) ? 1.0f : 0.0f;
    }
}

// ---------------------------------------------------------------------------
extern "C" void kernel_launch(void* const* d_in, const int* in_sizes, int n_in,
                              void* d_out, int out_size) {
    const float* a = (const float*)d_in[0];
    const float* b = (const float*)d_in[1];
    const float* rec = a;
    const float* wgt = b;
    if (in_sizes[0] > in_sizes[1]) { rec = b; wgt = a; }

    cudaFuncSetAttribute(gemm_kernel,
                         cudaFuncAttributeMaxDynamicSharedMemorySize, SMEMB);

    dim3 grid(SPLITS, 4);
    gemm_kernel<<<grid, 256, SMEMB>>>(wgt, rec);
    reduce_sel_kernel<<<RS_BLOCKS, 512>>>((float*)d_out);
}

// round 17
// speedup vs baseline: 1.0333x; 1.0333x over previous
#include <cuda_runtime.h>
#include <cuda_bf16.h>
#include <cstdint>

// ---------------------------------------------------------------------------
// Problem constants
#define NRED   100000
#define TT     32
#define KFEAT  512
#define THRESH 10.0f
#define KWTA   16

// GEMM tiling: 74 k-splits x 4 m-tiles = 296 CTAs (2 CTAs/SM)  [R7/R15 proven]
#define SPLITS 74
#define KTILE  64
#define NT     22
#define CHUNK  (KTILE * NT)        // 1408
#define MTILE  128

#define SM_A    0
#define SM_ASTG 32768
#define SM_B    (2 * SM_ASTG)      // 65536
#define SM_BSTG 8192
#define SMEMB   (SM_B + 2 * SM_BSTG)   // 81920

#define RS_BLOCKS 128              // reduce_sel grid

// Device scratch (static — no dynamic allocation allowed)
__device__ float g_partial[SPLITS * TT * KFEAT];
__device__ float g_dot[TT * KFEAT];                // [t][feat]
__device__ int   g_arrive;                         // last-block counter

typedef unsigned long long ull;

// ---------------------------------------------------------------------------
__device__ __forceinline__ uint32_t smem_u32(const void* p) {
    uint32_t a;
    asm("{ .reg .u64 t; cvta.to.shared.u64 t, %1; cvt.u32.u64 %0, t; }"
        : "=r"(a) : "l"(p));
    return a;
}
__device__ __forceinline__ uint32_t sw128(uint32_t off) {
    return off ^ ((off >> 3) & 0x70);
}
__device__ __forceinline__ uint32_t packbf(__nv_bfloat16 a, __nv_bfloat16 b) {
    __nv_bfloat162 v; v.x = a; v.y = b;
    return *reinterpret_cast<uint32_t*>(&v);
}
__device__ __forceinline__ void split2(float x, __nv_bfloat16& h, __nv_bfloat16& l) {
    h = __float2bfloat16(x);
    l = __float2bfloat16(x - __bfloat162float(h));
}
#define LDSM4(R, ADDR)                                                        \
    asm volatile("ldmatrix.sync.aligned.m8n8.x4.shared.b16 {%0,%1,%2,%3}, [%4];" \
                 : "=r"((R)[0]), "=r"((R)[1]), "=r"((R)[2]), "=r"((R)[3])     \
                 : "r"(ADDR))
#define MMA16816(D, A, B0, B1)                                                \
    asm volatile("mma.sync.aligned.m16n8k16.row.col.f32.bf16.bf16.f32 "       \
                 "{%0,%1,%2,%3}, {%4,%5,%6,%7}, {%8,%9}, {%0,%1,%2,%3};"      \
                 : "+f"((D)[0]), "+f"((D)[1]), "+f"((D)[2]), "+f"((D)[3])     \
                 : "r"((A)[0]), "r"((A)[1]), "r"((A)[2]), "r"((A)[3]),        \
                   "r"(B0), "r"(B1))

// ---------------------------------------------------------------------------
// GEMM: bf16 3-term split, R-split fused into the B loader.
// grid (74, 4), 256 threads, 2 CTAs/SM.  [R15 structure, reverted from R16]
// ---------------------------------------------------------------------------
__global__ void __launch_bounds__(256, 2)
gemm_kernel(const float* __restrict__ W, const float* __restrict__ R) {
    extern __shared__ char smem[];
    const uint32_t sb = smem_u32(smem);

    const int tid  = threadIdx.x;
    const int lane = tid & 31;
    const int wrp  = tid >> 5;
    const int q    = wrp & 3;
    const int grp  = wrp >> 2;
    const int split = blockIdx.x;
    const int m0    = blockIdx.y * MTILE;
    const int kbase = split * CHUNK;

    if (split == 0 && blockIdx.y == 0 && tid == 0) g_arrive = 0;

    const int row_off = lane >> 4;
    const int kq      = lane & 15;
    const int bt  = tid >> 3;
    const int bkc = tid & 7;
    const uint32_t bo = (uint32_t)bt * 128 + (uint32_t)bkc * 16;

    const int s0 = 2 * q, s1 = 2 * q + 1;
    const int arow0 = s0 * 16 + (lane & 7) + ((lane >> 3) & 1) * 8;
    const int arow1 = s1 * 16 + (lane & 7) + ((lane >> 3) & 1) * 8;
    const uint32_t a_kb0 = ((lane >> 4) & 1) * 16;
    const uint32_t a_off0 = (uint32_t)arow0 * 128;
    const uint32_t a_off1 = (uint32_t)arow1 * 128;
    const uint32_t a_xr0  = (uint32_t)(arow0 & 7) << 4;
    const uint32_t a_xr1  = (uint32_t)(arow1 & 7) << 4;
    const int browl = (lane & 7) + ((lane >> 4) & 1) * 8;
    const uint32_t b_rb  = (uint32_t)browl * 128 + (uint32_t)grp * 4096;
    const uint32_t b_xr  = (uint32_t)(lane & 7) << 4;
    const uint32_t b_kb0 = ((lane >> 3) & 1) * 16;

    float d[2][4][4];
#pragma unroll
    for (int s = 0; s < 2; s++)
#pragma unroll
        for (int i = 0; i < 4; i++)
#pragma unroll
            for (int j = 0; j < 4; j++) d[s][i][j] = 0.0f;

    float4 wr[8];
    float4 br0, br1;
    const float4 z4 = make_float4(0.f, 0.f, 0.f, 0.f);

#define LOAD_W(TL) do {                                                      \
    const int kp_ = kbase + (TL) * KTILE + kq * 4;                           \
    const bool ok_ = (kp_ < NRED);                                           \
    const float* wp_ = W + (size_t)(m0 + wrp * 2 + row_off) * NRED + kp_;    \
    _Pragma("unroll")                                                        \
    for (int i = 0; i < 8; i++)                                              \
        wr[i] = ok_ ? *(const float4*)(wp_ + (size_t)16 * i * NRED) : z4;    \
} while (0)

#define LOAD_B(TL) do {                                                      \
    const int kp_ = kbase + (TL) * KTILE + bkc * 8;                          \
    const bool ok_ = (kp_ < NRED);                                           \
    const float* rp_ = R + (size_t)bt * NRED + kp_;                          \
    br0 = ok_ ? *(const float4*)(rp_)     : z4;                              \
    br1 = ok_ ? *(const float4*)(rp_ + 4) : z4;                              \
} while (0)

#define STS_B(BUF) do {                                                      \
    char* bb_ = smem + SM_B + (BUF) * SM_BSTG;                               \
    __nv_bfloat16 h0,h1,h2,h3,h4,h5,h6,h7,l0,l1,l2,l3,l4,l5,l6,l7;           \
    split2(br0.x,h0,l0); split2(br0.y,h1,l1);                                \
    split2(br0.z,h2,l2); split2(br0.w,h3,l3);                                \
    split2(br1.x,h4,l4); split2(br1.y,h5,l5);                                \
    split2(br1.z,h6,l6); split2(br1.w,h7,l7);                                \
    *(uint4*)(bb_ + sw128(bo)) =                                             \
        make_uint4(packbf(h0,h1), packbf(h2,h3), packbf(h4,h5), packbf(h6,h7)); \
    *(uint4*)(bb_ + sw128(bo + 4096)) =                                      \
        make_uint4(packbf(l0,l1), packbf(l2,l3), packbf(l4,l5), packbf(l6,l7)); \
} while (0)

#define STS_A(BUF) do {                                                      \
    char* ab_ = smem + SM_A + (BUF) * SM_ASTG;                               \
    _Pragma("unroll")                                                        \
    for (int i = 0; i < 8; i++) {                                            \
        const int row_ = i * 16 + wrp * 2 + row_off;                         \
        const uint32_t sw_ = sw128((uint32_t)row_ * 128 + kq * 8);           \
        float4 f_ = wr[i];                                                   \
        __nv_bfloat16 h0,h1,h2,h3,l0,l1,l2,l3;                               \
        split2(f_.x, h0, l0); split2(f_.y, h1, l1);                          \
        split2(f_.z, h2, l2); split2(f_.w, h3, l3);                          \
        *(uint2*)(ab_ + sw_)         = make_uint2(packbf(h0,h1), packbf(h2,h3)); \
        *(uint2*)(ab_ + sw_ + 16384) = make_uint2(packbf(l0,l1), packbf(l2,l3)); \
    }                                                                        \
} while (0)

#define COMPUTE(BUF) do {                                                    \
    const uint32_t sa_ = sb + SM_A + (BUF) * SM_ASTG;                        \
    const uint32_t sB_ = sb + SM_B + (BUF) * SM_BSTG;                        \
    _Pragma("unroll")                                                        \
    for (int ks = 0; ks < 4; ks++) {                                         \
        uint32_t ah0[4], ah1[4], bf[2][4];                                   \
        const uint32_t kb_ = (uint32_t)(ks * 32) + a_kb0;                    \
        LDSM4(ah0, sa_ + a_off0 + (kb_ ^ a_xr0));                            \
        LDSM4(ah1, sa_ + a_off1 + (kb_ ^ a_xr1));                            \
        const uint32_t bkb_ = ((uint32_t)(ks * 32) + b_kb0) ^ b_xr;          \
        LDSM4(bf[0], sB_ + b_rb + bkb_);                                     \
        LDSM4(bf[1], sB_ + 2048 + b_rb + bkb_);                              \
        MMA16816(d[0][0], ah0, bf[0][0], bf[0][1]);                          \
        MMA16816(d[0][1], ah0, bf[0][2], bf[0][3]);                          \
        MMA16816(d[0][2], ah0, bf[1][0], bf[1][1]);                          \
        MMA16816(d[0][3], ah0, bf[1][2], bf[1][3]);                          \
        MMA16816(d[1][0], ah1, bf[0][0], bf[0][1]);                          \
        MMA16816(d[1][1], ah1, bf[0][2], bf[0][3]);                          \
        MMA16816(d[1][2], ah1, bf[1][0], bf[1][1]);                          \
        MMA16816(d[1][3], ah1, bf[1][2], bf[1][3]);                          \
        if (grp == 0) {                                                      \
            uint32_t al0[4], al1[4];                                         \
            LDSM4(al0, sa_ + 16384 + a_off0 + (kb_ ^ a_xr0));                \
            LDSM4(al1, sa_ + 16384 + a_off1 + (kb_ ^ a_xr1));                \
            MMA16816(d[0][0], al0, bf[0][0], bf[0][1]);                      \
            MMA16816(d[0][1], al0, bf[0][2], bf[0][3]);                      \
            MMA16816(d[0][2], al0, bf[1][0], bf[1][1]);                      \
            MMA16816(d[0][3], al0, bf[1][2], bf[1][3]);                      \
            MMA16816(d[1][0], al1, bf[0][0], bf[0][1]);                      \
            MMA16816(d[1][1], al1, bf[0][2], bf[0][3]);                      \
            MMA16816(d[1][2], al1, bf[1][0], bf[1][1]);                      \
            MMA16816(d[1][3], al1, bf[1][2], bf[1][3]);                      \
        }                                                                    \
    }                                                                        \
} while (0)

    LOAD_B(0);
    LOAD_W(0);
    STS_B(0);
    STS_A(0);
    __syncthreads();

    for (int tl = 0; tl < NT; tl++) {
        if (tl + 1 < NT) {
            LOAD_B(tl + 1);
            LOAD_W(tl + 1);
        }
        COMPUTE(tl & 1);
        if (tl + 1 < NT) {
            STS_B((tl + 1) & 1);
            STS_A((tl + 1) & 1);
            __syncthreads();
        }
    }

    __syncthreads();
    float* es = (float*)smem;
    const int eidx = (q * 32 + lane) * 33;
    if (grp == 1) {
#pragma unroll
        for (int s = 0; s < 2; s++)
#pragma unroll
            for (int i = 0; i < 4; i++)
#pragma unroll
                for (int j = 0; j < 4; j++)
                    es[eidx + s * 16 + i * 4 + j] = d[s][i][j];
    }
    __syncthreads();
    if (grp == 0) {
        float* gp = g_partial + (size_t)split * (TT * KFEAT) + m0;
        const int rbase = lane >> 2;
        const int c0 = (lane & 3) * 2;
#pragma unroll
        for (int s = 0; s < 2; s++) {
            const int feat = (2 * q + s) * 16 + rbase;
#pragma unroll
            for (int nt = 0; nt < 4; nt++) {
                const int t0 = nt * 8 + c0;
                float v0 = d[s][nt][0] + es[eidx + s * 16 + nt * 4 + 0];
                float v1 = d[s][nt][1] + es[eidx + s * 16 + nt * 4 + 1];
                float v2 = d[s][nt][2] + es[eidx + s * 16 + nt * 4 + 2];
                float v3 = d[s][nt][3] + es[eidx + s * 16 + nt * 4 + 3];
                gp[(size_t)t0 * KFEAT + feat]           = v0;
                gp[(size_t)(t0 + 1) * KFEAT + feat]     = v1;
                gp[(size_t)t0 * KFEAT + feat + 8]       = v2;
                gp[(size_t)(t0 + 1) * KFEAT + feat + 8] = v3;
            }
        }
    }
}

// ---------------------------------------------------------------------------
// Fused reduce + selection. 128 blocks x 512 threads.
// Election fences are now single-thread (threadfenceReduction pattern):
// __syncthreads gives intra-block HB; tid0's release fence publishes the
// block's g_dot writes; last block's tid0 acquire fence + syncthreads orders
// the selection reads. No per-thread MEMBAR.GPU / L1 flush storm.
// ---------------------------------------------------------------------------
__global__ void __launch_bounds__(512, 1)
reduce_sel_kernel(float* __restrict__ out) {
    __shared__ float part_s[4][136];
    const int k = threadIdx.x;
    {
        const int jl = k & 127;
        const int p  = k >> 7;
        const int j  = blockIdx.x * 128 + jl;
        const int sp0 = (p * SPLITS) >> 2;
        const int sp1 = ((p + 1) * SPLITS) >> 2;
        float s = 0.0f;
#pragma unroll 8
        for (int sp = sp0; sp < sp1; sp++)
            s += g_partial[sp * (TT * KFEAT) + j];
        part_s[p][jl] = s;
        __syncthreads();
        if (k < 128) {
            float tot = ((part_s[0][k] + part_s[1][k])
                       + (part_s[2][k] + part_s[3][k]));
            g_dot[blockIdx.x * 128 + k] = tot;
        }
    }

    __shared__ int is_last;
    __syncthreads();
    if (k == 0) {
        __threadfence();   // release: publish this block's g_dot writes
        is_last = (atomicAdd(&g_arrive, 1) == RS_BLOCKS - 1);
        if (is_last) __threadfence();   // acquire: see all blocks' g_dot
    }
    __syncthreads();
    if (!is_last) return;

    // ---- selection phase (last block only) ----
    __shared__ ull   key_s[KFEAT];
    __shared__ int   win_s[KFEAT];
    __shared__ float red_s[16];
    __shared__ float v_s;

    int nspk = 0;
#pragma unroll
    for (int t = 0; t < TT; t++) {
        float dd = g_dot[t * KFEAT + k];
        nspk += (dd > THRESH) ? 1 : 0;
    }
    int first = TT - nspk;
    if (first > TT - 1) first = TT - 1;
    if (first < 0) first = 0;
    float dv = g_dot[first * KFEAT + k];
    float value = (dv > THRESH) ? dv : 0.0f;
    float sval = (nspk > 0) ? value : 0.0f;

    float m = sval;
#pragma unroll
    for (int o = 16; o > 0; o >>= 1)
        m = fmaxf(m, __shfl_xor_sync(0xffffffffu, m, o));
    if ((k & 31) == 0) red_s[k >> 5] = m;
    win_s[k] = 0;
    __syncthreads();
    if (k == 0) {
        float mm = red_s[0];
#pragma unroll
        for (int i = 1; i < 16; i++) mm = fmaxf(mm, red_s[i]);
        v_s = mm * (float)TT;
    }
    __syncthreads();

    const float fns = (float)nspk;
    const float total = fns * value + fns * v_s;   // >= 0 always
    ull key = ((ull)__float_as_uint(total) << 32)
            | (ull)(KFEAT - 1 - k);

#define INTRA_STAGE(KK, J) do {                                              \
    ull other_ = __shfl_xor_sync(0xffffffffu, key, (J));                     \
    const bool up_ = ((k & (KK)) == 0);                                      \
    const bool lo_ = ((k & (J)) == 0);                                       \
    const bool keepmin_ = (up_ == lo_);                                      \
    key = keepmin_ ? (key < other_ ? key : other_)                           \
                   : (key > other_ ? key : other_);                          \
} while (0)

#define CROSS_STAGE(KK, J) do {                                              \
    key_s[k] = key;                                                          \
    __syncthreads();                                                         \
    ull other_ = key_s[k ^ (J)];                                             \
    const bool up_ = ((k & (KK)) == 0);                                      \
    const bool lo_ = ((k & (J)) == 0);                                       \
    const bool keepmin_ = (up_ == lo_);                                      \
    key = keepmin_ ? (key < other_ ? key : other_)                           \
                   : (key > other_ ? key : other_);                          \
    __syncthreads();                                                         \
} while (0)

    INTRA_STAGE(2, 1);
    INTRA_STAGE(4, 2);  INTRA_STAGE(4, 1);
    INTRA_STAGE(8, 4);  INTRA_STAGE(8, 2);  INTRA_STAGE(8, 1);
    INTRA_STAGE(16, 8); INTRA_STAGE(16, 4); INTRA_STAGE(16, 2); INTRA_STAGE(16, 1);
    INTRA_STAGE(32, 16); INTRA_STAGE(32, 8); INTRA_STAGE(32, 4);
    INTRA_STAGE(32, 2);  INTRA_STAGE(32, 1);
    CROSS_STAGE(64, 32);
    INTRA_STAGE(64, 16); INTRA_STAGE(64, 8); INTRA_STAGE(64, 4);
    INTRA_STAGE(64, 2);  INTRA_STAGE(64, 1);
    CROSS_STAGE(128, 64); CROSS_STAGE(128, 32);
    INTRA_STAGE(128, 16); INTRA_STAGE(128, 8); INTRA_STAGE(128, 4);
    INTRA_STAGE(128, 2);  INTRA_STAGE(128, 1);
    CROSS_STAGE(256, 128); CROSS_STAGE(256, 64); CROSS_STAGE(256, 32);
    INTRA_STAGE(256, 16); INTRA_STAGE(256, 8); INTRA_STAGE(256, 4);
    INTRA_STAGE(256, 2);  INTRA_STAGE(256, 1);
    CROSS_STAGE(512, 256); CROSS_STAGE(512, 128); CROSS_STAGE(512, 64);
    CROSS_STAGE(512, 32);
    INTRA_STAGE(512, 16); INTRA_STAGE(512, 8); INTRA_STAGE(512, 4);
    INTRA_STAGE(512, 2);  INTRA_STAGE(512, 1);

    if (k >= KFEAT - KWTA) {
        if ((uint32_t)(key >> 32) != 0u) {
            const int idx = KFEAT - 1 - (int)(key & 0x1ffull);
            win_s[idx] = 1;
        }
    }
    __syncthreads();

    const bool win = (win_s[k] != 0);
#pragma unroll
    for (int t = 0; t < TT; t++) {
        float dd = g_dot[t * KFEAT + k];
        out[t * KFEAT + k] = (win && dd > THRESH) ? 1.0f : 0.0f;
    }
}

// ---------------------------------------------------------------------------
extern "C" void kernel_launch(void* const* d_in, const int* in_sizes, int n_in,
                              void* d_out, int out_size) {
    const float* a = (const float*)d_in[0];
    const float* b = (const float*)d_in[1];
    const float* rec = a;
    const float* wgt = b;
    if (in_sizes[0] > in_sizes[1]) { rec = b; wgt = a; }

    cudaFuncSetAttribute(gemm_kernel,
                         cudaFuncAttributeMaxDynamicSharedMemorySize, SMEMB);

    dim3 grid(SPLITS, 4);
    gemm_kernel<<<grid, 256, SMEMB>>>(wgt, rec);
    reduce_sel_kernel<<<RS_BLOCKS, 512>>>((float*)d_out);
}